// round 8
// baseline (speedup 1.0000x reference)
#include <cuda_runtime.h>

#define VOL 262144   // 64*64*64 voxels

typedef unsigned long long u64;

__device__ __forceinline__ u64 pk2(float lo, float hi) {
    u64 r; asm("mov.b64 %0,{%1,%2};" : "=l"(r) : "f"(lo), "f"(hi)); return r;
}
__device__ __forceinline__ void upk2(u64 v, float& lo, float& hi) {
    asm("mov.b64 {%0,%1},%2;" : "=f"(lo), "=f"(hi) : "l"(v));
}
__device__ __forceinline__ void fma2(u64& d, u64 a, u64 b) {
    asm("fma.rn.f32x2 %0,%1,%2,%0;" : "+l"(d) : "l"(a), "l"(b));
}

// ---------------- device-global precomputed weights (scratch; no allocs) ----------------
__device__ __align__(16) float g_WQKVT[128 * 384]; // folded qkv weights TRANSPOSED: [c][o] (q rows pre-scaled)
__device__ __align__(16) float g_QB[384];          // folded qkv bias (q part pre-scaled)
__device__ __align__(16) float g_P[64 * 128];      // proj_w[:64] + proj_w[64:]  [c][k]
__device__ float g_PB[64];                         // proj_b[:64] + proj_b[64:]
__device__ __align__(16) float g_BIAS[4 * 64 * 64];// dense rel-pos bias [h][i][j]

// ---------------- prep kernel ----------------
__global__ void prep_kernel(const float* __restrict__ conv_w, const float* __restrict__ conv_b,
                            const float* __restrict__ trans_w, const float* __restrict__ trans_b,
                            const float* __restrict__ qkv_w, const float* __restrict__ qkv_b,
                            const float* __restrict__ proj_w, const float* __restrict__ proj_b,
                            const float* __restrict__ table, const int* __restrict__ ridx)
{
    const float SCALE = 0.17677669529663688f;  // 32^-0.5
    int id = blockIdx.x * blockDim.x + threadIdx.x;
    if (id < 49152) {                       // WQKVT[c][o]
        int c = id / 384, o = id % 384;
        float s = 0.f;
        if (c < 64) {
            const float* qw = qkv_w + o * 128;
            #pragma unroll 8
            for (int m = 0; m < 64; m++) s += qw[m] * conv_w[m * 64 + c];
        } else {
            const float* qw = qkv_w + o * 128 + 64;
            int cc = c - 64;
            #pragma unroll 8
            for (int m = 0; m < 64; m++) s += qw[m] * trans_w[m * 64 + cc];
        }
        if (o < 128) s *= SCALE;            // fold attention scale into q
        g_WQKVT[id] = s;
    } else if (id < 49536) {                // QB
        int o = id - 49152;
        float s = qkv_b[o];
        const float* qw = qkv_w + o * 128;
        #pragma unroll 8
        for (int m = 0; m < 64; m++) s += qw[m] * conv_b[m] + qw[64 + m] * trans_b[m];
        if (o < 128) s *= SCALE;
        g_QB[o] = s;
    } else if (id < 57728) {                // P[c][k]
        int p = id - 49536;
        int c = p >> 7, k = p & 127;
        g_P[p] = proj_w[c * 128 + k] + proj_w[(c + 64) * 128 + k];
    } else if (id < 57792) {                // PB
        int c = id - 57728;
        g_PB[c] = proj_b[c] + proj_b[c + 64];
    } else if (id < 74176) {                // BIAS[h][i][j]
        int x = id - 57792;
        int h = x >> 12, ij = x & 4095;
        g_BIAS[x] = table[ridx[ij] * 4 + h];
    }
}

// ---------------- fused per-window kernel (256 threads) ----------------
// smem layout (floats):
//   feat : [128] x 17 float4             @ 0      .. 8704
//   qT   : [256 o][64 t] chunk-swizzled  @ 8704   .. 25088   (q rows 0-127, k rows 128-255)
//   vTok : [64 t] x 33 ulonglong2        @ 25088  .. 33536   (v token-major, unit-swizzled)
//   wt   : [128 c] x 33 float4           @ 33536  .. 50432   (phase2 weight tile)
//   PT   : [4 h][64 j][64 i] swizzled    @ 33536  .. 49920   (aliases wt, after sync)
//   ps   : [64] x 33 float4              @ 33536  .. 41984   (aliases PT, after sync)
//   outs : [64] x 33 ulonglong2          @ 8704   .. 17152   (aliases qT, after sync)
// total 50432 floats = 201728 bytes

__global__ void __launch_bounds__(256, 1)
fused_attn_kernel(const float* __restrict__ conv_feat,
                  const float* __restrict__ trans_feat,
                  float* __restrict__ out)
{
    extern __shared__ float sm[];
    float* feat = sm;
    float4* feat4 = (float4*)sm;                     // stride 17
    float* qT = sm + 8704;                           // [o][64]
    ulonglong2* vu = (ulonglong2*)(sm + 25088);      // stride 33 per token
    float4* wt4 = (float4*)(sm + 33536);             // stride 33 per c
    ulonglong2* wtu = (ulonglong2*)(sm + 33536);
    float* smPT = sm + 33536;                        // [h][j][64]
    float4* ps4 = (float4*)(sm + 33536);             // stride 33
    ulonglong2* psu = (ulonglong2*)(sm + 33536);
    float* outsf = sm + 8704;                        // [t][132]
    ulonglong2* outsu = (ulonglong2*)(sm + 8704);    // stride 33

    const int tid = threadIdx.x;
    const int wb = blockIdx.x;
    const int base = ((wb >> 8) * 4) * 4096 + (((wb >> 4) & 15) * 4) * 64 + (wb & 15) * 4;

    // ---- Phase 1: load cf/tf window tiles (channel-major [c][t]) ----
    #pragma unroll
    for (int k = 0; k < 8; k++) {
        int v = k * 256 + tid;
        int vv = v & 1023;
        int c = vv >> 4;
        int r16 = vv & 15;
        const float* src = (v < 1024) ? conv_feat : trans_feat;
        float4 val = *(const float4*)(src + (size_t)c * VOL + base + (r16 >> 2) * 4096 + (r16 & 3) * 64);
        int row = (v < 1024) ? c : (64 + c);
        feat4[row * 17 + r16] = val;
    }
    __syncthreads();

    // ---- Phase 2: qkv projections; q/k stored dim-major, v token-major ----
    const int tx = tid & 15;   // token group (4 tokens: t = tx*4+m)
    const int ty = tid >> 4;   // output group (8 outputs per 128-chunk)
    const int sx = tx & 7;
    const float4* gW4 = (const float4*)g_WQKVT;  // [c][96] float4

    #pragma unroll
    for (int chunk = 0; chunk < 3; chunk++) {
        const int ob = chunk * 128;
        #pragma unroll
        for (int k = 0; k < 16; k++) {
            int f = k * 256 + tid;
            int c = f >> 5, o4 = f & 31;
            wt4[c * 33 + o4] = gW4[c * 96 + (ob >> 2) + o4];
        }
        __syncthreads();

        u64 acc[4][4];   // [o-pair][token m]
        {
            float qb[8];
            #pragma unroll
            for (int r = 0; r < 8; r++) qb[r] = g_QB[ob + ty * 8 + r];
            #pragma unroll
            for (int op = 0; op < 4; op++) {
                u64 b2 = pk2(qb[op * 2], qb[op * 2 + 1]);
                acc[op][0] = b2; acc[op][1] = b2; acc[op][2] = b2; acc[op][3] = b2;
            }
        }
        #pragma unroll 4
        for (int c = 0; c < 128; c++) {
            float4 fv = feat4[c * 17 + tx];
            ulonglong2 wv0 = wtu[c * 33 + ty * 2];
            ulonglong2 wv1 = wtu[c * 33 + ty * 2 + 1];
            u64 d0 = pk2(fv.x, fv.x), d1 = pk2(fv.y, fv.y);
            u64 d2 = pk2(fv.z, fv.z), d3 = pk2(fv.w, fv.w);
            fma2(acc[0][0], wv0.x, d0); fma2(acc[1][0], wv0.y, d0);
            fma2(acc[2][0], wv1.x, d0); fma2(acc[3][0], wv1.y, d0);
            fma2(acc[0][1], wv0.x, d1); fma2(acc[1][1], wv0.y, d1);
            fma2(acc[2][1], wv1.x, d1); fma2(acc[3][1], wv1.y, d1);
            fma2(acc[0][2], wv0.x, d2); fma2(acc[1][2], wv0.y, d2);
            fma2(acc[2][2], wv1.x, d2); fma2(acc[3][2], wv1.y, d2);
            fma2(acc[0][3], wv0.x, d3); fma2(acc[1][3], wv0.y, d3);
            fma2(acc[2][3], wv1.x, d3); fma2(acc[3][3], wv1.y, d3);
        }
        if (chunk < 2) {
            // q/k: store dim-major qT[o][t], token-chunks XOR-swizzled by (o>>3)&7
            float fa[8][4];
            #pragma unroll
            for (int op = 0; op < 4; op++)
                #pragma unroll
                for (int m = 0; m < 4; m++)
                    upk2(acc[op][m], fa[op * 2][m], fa[op * 2 + 1][m]);
            #pragma unroll
            for (int r = 0; r < 8; r++) {
                int o = ob + ty * 8 + r;
                int key = (o >> 3) & 7;
                *(float4*)(qT + o * 64 + ((tx ^ key) << 2)) =
                    make_float4(fa[r][0], fa[r][1], fa[r][2], fa[r][3]);
            }
        } else {
            // v: token-major vTok[t][32 units], units XOR-swizzled by (t>>2)&7
            #pragma unroll
            for (int r4 = 0; r4 < 2; r4++) {
                int u = ty * 2 + r4;
                #pragma unroll
                for (int m = 0; m < 4; m++) {
                    int t = tx * 4 + m;
                    ulonglong2 st;
                    st.x = acc[r4 * 2 + 0][m];
                    st.y = acc[r4 * 2 + 1][m];
                    vu[t * 33 + (u ^ sx)] = st;
                }
            }
        }
        __syncthreads();
    }

    // ---- Phase 3: attention as two outer-product GEMMs ----
    const int h  = tid >> 6;           // head (warp-pair uniform)
    const int u6 = tid & 63;
    const int a  = u6 >> 3, b = u6 & 7;
    const int i0 = a * 8, j0 = b * 8;
    float inv[8];

    {
        // S[i][j] = sum_d q[i,d]*k[j,d] + bias   (q pre-scaled)
        u64 sp[8][4];  // packed along j
        #pragma unroll
        for (int i = 0; i < 8; i++) {
            const float4* bb = (const float4*)(g_BIAS + (h * 64 + i0 + i) * 64 + j0);
            float4 b0 = bb[0], b1 = bb[1];
            sp[i][0] = pk2(b0.x, b0.y); sp[i][1] = pk2(b0.z, b0.w);
            sp[i][2] = pk2(b1.x, b1.y); sp[i][3] = pk2(b1.z, b1.w);
        }
        #pragma unroll 8
        for (int d = 0; d < 32; d++) {
            int key = ((h * 32 + d) >> 3) & 7;
            const float* qrow = qT + (h * 32 + d) * 64;
            const float* krow = qT + (128 + h * 32 + d) * 64;
            float4 q0 = *(const float4*)(qrow + (((2 * a + 0) ^ key) << 2));
            float4 q1 = *(const float4*)(qrow + (((2 * a + 1) ^ key) << 2));
            ulonglong2 kA = *(const ulonglong2*)(krow + (((2 * b + 0) ^ key) << 2));
            ulonglong2 kB = *(const ulonglong2*)(krow + (((2 * b + 1) ^ key) << 2));
            u64 kp0 = kA.x, kp1 = kA.y, kp2 = kB.x, kp3 = kB.y;
            float qf[8] = {q0.x, q0.y, q0.z, q0.w, q1.x, q1.y, q1.z, q1.w};
            #pragma unroll
            for (int i = 0; i < 8; i++) {
                u64 qd = pk2(qf[i], qf[i]);
                fma2(sp[i][0], qd, kp0); fma2(sp[i][1], qd, kp1);
                fma2(sp[i][2], qd, kp2); fma2(sp[i][3], qd, kp3);
            }
        }
        // softmax over rows i (reduce across the 8 b-lanes)
        float s[8][8];
        #pragma unroll
        for (int i = 0; i < 8; i++) {
            upk2(sp[i][0], s[i][0], s[i][1]); upk2(sp[i][1], s[i][2], s[i][3]);
            upk2(sp[i][2], s[i][4], s[i][5]); upk2(sp[i][3], s[i][6], s[i][7]);
        }
        #pragma unroll
        for (int i = 0; i < 8; i++) {
            float m = s[i][0];
            #pragma unroll
            for (int j = 1; j < 8; j++) m = fmaxf(m, s[i][j]);
            m = fmaxf(m, __shfl_xor_sync(0xFFFFFFFFu, m, 1));
            m = fmaxf(m, __shfl_xor_sync(0xFFFFFFFFu, m, 2));
            m = fmaxf(m, __shfl_xor_sync(0xFFFFFFFFu, m, 4));
            float sum = 0.f;
            #pragma unroll
            for (int j = 0; j < 8; j++) { s[i][j] = __expf(s[i][j] - m); sum += s[i][j]; }
            sum += __shfl_xor_sync(0xFFFFFFFFu, sum, 1);
            sum += __shfl_xor_sync(0xFFFFFFFFu, sum, 2);
            sum += __shfl_xor_sync(0xFFFFFFFFu, sum, 4);
            inv[i] = 1.f / sum;
        }
        // store P transposed: PT[h][j][i], i-chunks XOR-swizzled by (j>>3)&7 (== b)
        #pragma unroll
        for (int jj = 0; jj < 8; jj++) {
            float* prow = smPT + h * 4096 + (j0 + jj) * 64;
            *(float4*)(prow + (((2 * a + 0) ^ b) << 2)) =
                make_float4(s[0][jj], s[1][jj], s[2][jj], s[3][jj]);
            *(float4*)(prow + (((2 * a + 1) ^ b) << 2)) =
                make_float4(s[4][jj], s[5][jj], s[6][jj], s[7][jj]);
        }
    }
    __syncthreads();

    {
        // O[i][d] = sum_j P[i][j]*v[j][d]; thread: 4 i-pairs x 4 d-cols (unit h*8+b)
        u64 o_[4][4];
        #pragma unroll
        for (int ip = 0; ip < 4; ip++)
            #pragma unroll
            for (int dc = 0; dc < 4; dc++) o_[ip][dc] = 0ull;

        #pragma unroll 8
        for (int j = 0; j < 64; j++) {
            const float* prow = smPT + h * 4096 + j * 64;
            int kj = (j >> 3) & 7;
            ulonglong2 pA = *(const ulonglong2*)(prow + (((2 * a + 0) ^ kj) << 2));
            ulonglong2 pB = *(const ulonglong2*)(prow + (((2 * a + 1) ^ kj) << 2));
            int kv = (j >> 2) & 7;
            ulonglong2 vv = vu[j * 33 + ((h * 8 + b) ^ kv)];
            float v0, v1, v2, v3;
            upk2(vv.x, v0, v1); upk2(vv.y, v2, v3);
            u64 vd0 = pk2(v0, v0), vd1 = pk2(v1, v1), vd2 = pk2(v2, v2), vd3 = pk2(v3, v3);
            u64 pp0 = pA.x, pp1 = pA.y, pp2 = pB.x, pp3 = pB.y;
            fma2(o_[0][0], pp0, vd0); fma2(o_[0][1], pp0, vd1);
            fma2(o_[0][2], pp0, vd2); fma2(o_[0][3], pp0, vd3);
            fma2(o_[1][0], pp1, vd0); fma2(o_[1][1], pp1, vd1);
            fma2(o_[1][2], pp1, vd2); fma2(o_[1][3], pp1, vd3);
            fma2(o_[2][0], pp2, vd0); fma2(o_[2][1], pp2, vd1);
            fma2(o_[2][2], pp2, vd2); fma2(o_[2][3], pp2, vd3);
            fma2(o_[3][0], pp3, vd0); fma2(o_[3][1], pp3, vd1);
            fma2(o_[3][2], pp3, vd2); fma2(o_[3][3], pp3, vd3);
        }
        __syncthreads();   // all PT/vTok/qT reads done; safe to overwrite below

        // normalize + store outs[t][k] (k-unit = h*8+b), rows i0+2ip, i0+2ip+1
        #pragma unroll
        for (int ip = 0; ip < 4; ip++) {
            float oa[4], obv[4];
            upk2(o_[ip][0], oa[0], obv[0]); upk2(o_[ip][1], oa[1], obv[1]);
            upk2(o_[ip][2], oa[2], obv[2]); upk2(o_[ip][3], oa[3], obv[3]);
            float ia = inv[ip * 2], ib = inv[ip * 2 + 1];
            int iA = i0 + ip * 2;
            *(float4*)(outsf + iA * 132 + (h * 8 + b) * 4) =
                make_float4(oa[0] * ia, oa[1] * ia, oa[2] * ia, oa[3] * ia);
            *(float4*)(outsf + (iA + 1) * 132 + (h * 8 + b) * 4) =
                make_float4(obv[0] * ib, obv[1] * ib, obv[2] * ib, obv[3] * ib);
        }
    }

    // stage proj tile (overlays PT; PT dead after post-PV sync)
    #pragma unroll
    for (int k = 0; k < 8; k++) {
        int f = k * 256 + tid;
        ps4[(f >> 5) * 33 + (f & 31)] = *((const float4*)g_P + f);
    }
    __syncthreads();

    // ---- Phase 4: final[t][c] = sum_k outs[t][k]*P[c][k] + PB[c] + conv_feat[c][t] ----
    {
        u64 acc2[4][4];
        #pragma unroll
        for (int r = 0; r < 4; r++)
            #pragma unroll
            for (int m = 0; m < 4; m++) acc2[r][m] = 0ull;

        #pragma unroll 4
        for (int k4 = 0; k4 < 32; k4++) {
            ulonglong2 pr[4], ovv[4];
            #pragma unroll
            for (int r = 0; r < 4; r++) pr[r] = psu[(ty * 4 + r) * 33 + k4];
            #pragma unroll
            for (int m = 0; m < 4; m++) ovv[m] = outsu[(m * 16 + tx) * 33 + k4];
            #pragma unroll
            for (int r = 0; r < 4; r++)
                #pragma unroll
                for (int m = 0; m < 4; m++) {
                    fma2(acc2[r][m], pr[r].x, ovv[m].x);
                    fma2(acc2[r][m], pr[r].y, ovv[m].y);
                }
        }
        int dy = tx >> 2, dx = tx & 3;
        #pragma unroll
        for (int r = 0; r < 4; r++) {
            int c = ty * 4 + r;
            float pb = g_PB[c];
            #pragma unroll
            for (int m = 0; m < 4; m++) {
                int t = m * 16 + tx;
                float lo, hi;
                upk2(acc2[r][m], lo, hi);
                float cf = feat[c * 68 + t];
                out[(size_t)c * VOL + base + m * 4096 + dy * 64 + dx] = (lo + hi) + pb + cf;
            }
        }
    }
}

// ---------------- launch ----------------
extern "C" void kernel_launch(void* const* d_in, const int* in_sizes, int n_in,
                              void* d_out, int out_size)
{
    const float* conv_feat  = (const float*)d_in[0];
    const float* trans_feat = (const float*)d_in[1];
    const float* conv_w     = (const float*)d_in[2];
    const float* conv_b     = (const float*)d_in[3];
    const float* trans_w    = (const float*)d_in[4];
    const float* trans_b    = (const float*)d_in[5];
    const float* qkv_w      = (const float*)d_in[6];
    const float* qkv_b      = (const float*)d_in[7];
    const float* proj_w     = (const float*)d_in[8];
    const float* proj_b     = (const float*)d_in[9];
    const float* table      = (const float*)d_in[10];
    const int*   ridx       = (const int*)d_in[11];
    float* o = (float*)d_out;

    cudaFuncSetAttribute(fused_attn_kernel, cudaFuncAttributeMaxDynamicSharedMemorySize, 201728);

    prep_kernel<<<290, 256>>>(conv_w, conv_b, trans_w, trans_b,
                              qkv_w, qkv_b, proj_w, proj_b, table, ridx);
    fused_attn_kernel<<<4096, 256, 201728>>>(conv_feat, trans_feat, o);
}

// round 11
// speedup vs baseline: 1.7314x; 1.7314x over previous
#include <cuda_runtime.h>
#include <cuda_bf16.h>
#include <cstdint>
#define VOL 262144
typedef unsigned long long u64;
typedef unsigned int u32;

__device__ __forceinline__ u64 pk2(float lo, float hi){u64 r;asm("mov.b64 %0,{%1,%2};":"=l"(r):"f"(lo),"f"(hi));return r;}
__device__ __forceinline__ void upk2(u64 v,float&lo,float&hi){asm("mov.b64 {%0,%1},%2;":"=f"(lo),"=f"(hi):"l"(v));}
__device__ __forceinline__ void fma2(u64&d,u64 a,u64 b){asm("fma.rn.f32x2 %0,%1,%2,%0;":"+l"(d):"l"(a),"l"(b));}
__device__ __forceinline__ u32 s2u(const void*p){u32 a;asm("{ .reg .u64 t; cvta.to.shared.u64 t,%1; cvt.u32.u64 %0,t; }":"=r"(a):"l"(p));return a;}
#define LDSM4(r0,r1,r2,r3,ad) asm volatile("ldmatrix.sync.aligned.m8n8.x4.shared.b16 {%0,%1,%2,%3},[%4];":"=r"(r0),"=r"(r1),"=r"(r2),"=r"(r3):"r"(ad))
#define MMA(c,a0,a1,a2,a3,b0,b1) asm volatile("mma.sync.aligned.m16n8k16.row.col.f32.bf16.bf16.f32 {%0,%1,%2,%3},{%4,%5,%6,%7},{%8,%9},{%0,%1,%2,%3};" \
    :"+f"((c)[0]),"+f"((c)[1]),"+f"((c)[2]),"+f"((c)[3]):"r"(a0),"r"(a1),"r"(a2),"r"(a3),"r"(b0),"r"(b1))

// globals: weights pre-swizzled bf16 rows of 256B (row o-local, 128 c), per 128-o chunk
__device__ __align__(16) __nv_bfloat16 g_WBF16[3*16384];
__device__ __align__(16) float g_QB[384];
__device__ __align__(16) float g_P[64*128];
__device__ float g_PB[64];
__device__ __align__(16) float g_BIAS[4*64*64];

__global__ void prep_kernel(const float* __restrict__ conv_w,const float* __restrict__ conv_b,
    const float* __restrict__ trans_w,const float* __restrict__ trans_b,
    const float* __restrict__ qkv_w,const float* __restrict__ qkv_b,
    const float* __restrict__ proj_w,const float* __restrict__ proj_b,
    const float* __restrict__ table,const int* __restrict__ ridx){
    const float SCALE=0.17677669529663688f;
    int id=blockIdx.x*blockDim.x+threadIdx.x;
    if(id<49152){
        int c=id/384,o=id%384;float s=0.f;
        if(c<64){const float*qw=qkv_w+o*128;
            #pragma unroll 8
            for(int m=0;m<64;m++)s+=qw[m]*conv_w[m*64+c];
        }else{const float*qw=qkv_w+o*128+64;int cc=c-64;
            #pragma unroll 8
            for(int m=0;m<64;m++)s+=qw[m]*trans_w[m*64+cc];}
        if(o<128)s*=SCALE;
        int ch=o>>7,ol=o&127;
        u32 byte=(u32)ol*256u+(((u32)c*2u)^(((u32)ol&7u)<<4));
        g_WBF16[ch*16384+(byte>>1)]=__float2bfloat16(s);
    }else if(id<49536){
        int o=id-49152;float s=qkv_b[o];const float*qw=qkv_w+o*128;
        #pragma unroll 8
        for(int m=0;m<64;m++)s+=qw[m]*conv_b[m]+qw[64+m]*trans_b[m];
        if(o<128)s*=SCALE;g_QB[o]=s;
    }else if(id<57728){
        int p=id-49536;int c=p>>7,k=p&127;
        g_P[p]=proj_w[c*128+k]+proj_w[(c+64)*128+k];
    }else if(id<57792){int c=id-57728;g_PB[c]=proj_b[c]+proj_b[c+64];
    }else if(id<74176){int x=id-57792;int h=x>>12,ij=x&4095;g_BIAS[x]=table[ridx[ij]*4+h];}
}

// smem floats: feat[128][68]@0..8704, featB bf16@byte34816(16KB), WB bf16@byte51200(32KB),
// qT[256][64]@20992..37376, vTok(stride132)@37376..45824, PT@4352..20736,
// outs@20992(ovl qT), ps@37376(ovl vTok). total 45824 floats = 183296B
__global__ void __launch_bounds__(256,1)
fused_attn_kernel(const float* __restrict__ conv_feat,const float* __restrict__ trans_feat,float* __restrict__ out){
    extern __shared__ float sm[];
    float4* feat4=(float4*)sm;
    float* qTf=sm+20992;
    float* vtf=sm+37376;
    ulonglong2* vu=(ulonglong2*)(sm+37376);
    float* smPT=sm+4352;
    float* outsf=sm+20992;
    ulonglong2* outsu=(ulonglong2*)(sm+20992);
    float4* ps4=(float4*)(sm+37376);
    ulonglong2* psu=(ulonglong2*)(sm+37376);

    const int tid=threadIdx.x, wid=tid>>5, lane=tid&31;
    const int wb=blockIdx.x;
    const int base=((wb>>8)*4)*4096+(((wb>>4)&15)*4)*64+(wb&15)*4;
    const u32 sb=s2u(sm);
    const u32 fbB=sb+34816u, wbB=sb+51200u;

    // Phase 1: load window (channel-major)
    #pragma unroll
    for(int k=0;k<8;k++){
        int v=k*256+tid, vv=v&1023, c=vv>>4, r16=vv&15;
        const float* src=(v<1024)?conv_feat:trans_feat;
        float4 val=*(const float4*)(src+(size_t)c*VOL+base+(r16>>2)*4096+(r16&3)*64);
        feat4[((v<1024)?c:(64+c))*17+r16]=val;
    }
    __syncthreads();

    // featB bf16 [64 t][128 c], 256B rows, XOR key (t&7)<<4
    #pragma unroll
    for(int i=0;i<16;i++){
        int p=i*256+tid; int t=p&63, cp=p>>6; int c=cp*2;
        float f0=sm[c*68+t], f1=sm[(c+1)*68+t];
        u32 bb; asm("cvt.rn.satfinite.bf16x2.f32 %0,%1,%2;":"=r"(bb):"f"(f1),"f"(f0));
        u32 byte=(u32)t*256u+(((u32)c*2u)^(((u32)t&7u)<<4));
        *(u32*)((char*)sm+34816+byte)=bb;
    }

    // Phase 2: 3 chunks of 128 o; warp = 16-o m-tile; mma.sync bf16
    const uint4* wsrc=(const uint4*)g_WBF16;
    uint4* wdst=(uint4*)((char*)sm+51200);
    const int o0=wid*16;
    for(int ch=0;ch<3;ch++){
        #pragma unroll
        for(int i=0;i<8;i++) wdst[i*256+tid]=wsrc[ch*2048+i*256+tid];
        __syncthreads();
        float acc[8][4];
        #pragma unroll
        for(int p=0;p<8;p++){acc[p][0]=0.f;acc[p][1]=0.f;acc[p][2]=0.f;acc[p][3]=0.f;}
        #pragma unroll
        for(int kc=0;kc<8;kc++){
            int oa=o0+(lane&15);
            u32 koff=(u32)kc*32u+(((u32)lane>>4)<<4);
            u32 aad=wbB+(u32)oa*256u+(koff^(((u32)oa&7u)<<4));
            u32 a0,a1,a2,a3; LDSM4(a0,a1,a2,a3,aad);
            int g=lane>>3;
            #pragma unroll
            for(int p=0;p<4;p++){
                int tB=(2*p+(g>>1))*8+(lane&7);
                u32 kb=(u32)kc*32u+(((u32)g&1u)<<4);
                u32 bad=fbB+(u32)tB*256u+(kb^(((u32)tB&7u)<<4));
                u32 b0,b1,b2,b3; LDSM4(b0,b1,b2,b3,bad);
                MMA(acc[2*p],a0,a1,a2,a3,b0,b1);
                MMA(acc[2*p+1],a0,a1,a2,a3,b2,b3);
            }
        }
        // epilogue: D rows = o0+lane/4 (+8); cols t = p*8+(lane%4)*2, +1
        int r0l=o0+(lane>>2), r1l=r0l+8;
        float qb0=g_QB[ch*128+r0l], qb1=g_QB[ch*128+r1l];
        if(ch<2){
            int orow0=ch*128+r0l, orow1=ch*128+r1l;
            int k0=orow0&7, k1=orow1&7;
            #pragma unroll
            for(int p=0;p<8;p++){
                int tt=p*8+(lane&3)*2; int tc=tt>>2; int off=tt&2;
                *(float2*)(qTf+orow0*64+((tc^k0)<<2)+off)=make_float2(acc[p][0]+qb0,acc[p][1]+qb0);
                *(float2*)(qTf+orow1*64+((tc^k1)<<2)+off)=make_float2(acc[p][2]+qb1,acc[p][3]+qb1);
            }
        }else{
            int du0=r0l>>2, dl0=r0l&3, du1=r1l>>2, dl1=r1l&3;
            #pragma unroll
            for(int p=0;p<8;p++){
                int tt=p*8+(lane&3)*2; int sk=(tt>>2)&7;
                vtf[tt*132+((du0^sk)<<2)+dl0]=acc[p][0]+qb0;
                vtf[(tt+1)*132+((du0^sk)<<2)+dl0]=acc[p][1]+qb0;
                vtf[tt*132+((du1^sk)<<2)+dl1]=acc[p][2]+qb1;
                vtf[(tt+1)*132+((du1^sk)<<2)+dl1]=acc[p][3]+qb1;
            }
        }
        __syncthreads();
    }

    // Phase 3: attention as two outer-product GEMMs (fp32)
    const int h=tid>>6, u6=tid&63, a=u6>>3, b=u6&7;
    const int i0=a*8, j0=b*8;
    const int tx=tid&15, ty=tid>>4;
    float inv[8];
    {
        u64 sp[8][4];
        #pragma unroll
        for(int i=0;i<8;i++){
            const float4* bb=(const float4*)(g_BIAS+(h*64+i0+i)*64+j0);
            float4 b0=bb[0],b1=bb[1];
            sp[i][0]=pk2(b0.x,b0.y);sp[i][1]=pk2(b0.z,b0.w);
            sp[i][2]=pk2(b1.x,b1.y);sp[i][3]=pk2(b1.z,b1.w);
        }
        #pragma unroll 8
        for(int d=0;d<32;d++){
            int key=d&7;
            const float* qrow=qTf+(h*32+d)*64;
            const float* krow=qTf+(128+h*32+d)*64;
            float4 q0=*(const float4*)(qrow+(((2*a)^key)<<2));
            float4 q1=*(const float4*)(qrow+(((2*a+1)^key)<<2));
            ulonglong2 kA=*(const ulonglong2*)(krow+(((2*b)^key)<<2));
            ulonglong2 kB=*(const ulonglong2*)(krow+(((2*b+1)^key)<<2));
            float qf[8]={q0.x,q0.y,q0.z,q0.w,q1.x,q1.y,q1.z,q1.w};
            #pragma unroll
            for(int i=0;i<8;i++){
                u64 qd=pk2(qf[i],qf[i]);
                fma2(sp[i][0],qd,kA.x);fma2(sp[i][1],qd,kA.y);
                fma2(sp[i][2],qd,kB.x);fma2(sp[i][3],qd,kB.y);
            }
        }
        float s[8][8];
        #pragma unroll
        for(int i=0;i<8;i++){
            upk2(sp[i][0],s[i][0],s[i][1]);upk2(sp[i][1],s[i][2],s[i][3]);
            upk2(sp[i][2],s[i][4],s[i][5]);upk2(sp[i][3],s[i][6],s[i][7]);
        }
        #pragma unroll
        for(int i=0;i<8;i++){
            float m=s[i][0];
            #pragma unroll
            for(int j=1;j<8;j++)m=fmaxf(m,s[i][j]);
            m=fmaxf(m,__shfl_xor_sync(~0u,m,1));m=fmaxf(m,__shfl_xor_sync(~0u,m,2));m=fmaxf(m,__shfl_xor_sync(~0u,m,4));
            float sum=0.f;
            #pragma unroll
            for(int j=0;j<8;j++){s[i][j]=__expf(s[i][j]-m);sum+=s[i][j];}
            sum+=__shfl_xor_sync(~0u,sum,1);sum+=__shfl_xor_sync(~0u,sum,2);sum+=__shfl_xor_sync(~0u,sum,4);
            inv[i]=1.f/sum;
        }
        __syncthreads();   // PT overlays featB/WB/tf
        #pragma unroll
        for(int jj=0;jj<8;jj++){
            float* prow=smPT+h*4096+(j0+jj)*64;
            *(float4*)(prow+(((2*a)^b)<<2))=make_float4(s[0][jj],s[1][jj],s[2][jj],s[3][jj]);
            *(float4*)(prow+(((2*a+1)^b)<<2))=make_float4(s[4][jj],s[5][jj],s[6][jj],s[7][jj]);
        }
    }
    __syncthreads();
    {
        u64 o_[4][4];
        #pragma unroll
        for(int ip=0;ip<4;ip++)
            #pragma unroll
            for(int dc=0;dc<4;dc++)o_[ip][dc]=0ull;
        #pragma unroll 8
        for(int j=0;j<64;j++){
            const float* prow=smPT+h*4096+j*64;
            int kj=(j>>3)&7;
            ulonglong2 pA=*(const ulonglong2*)(prow+(((2*a)^kj)<<2));
            ulonglong2 pB=*(const ulonglong2*)(prow+(((2*a+1)^kj)<<2));
            ulonglong2 vv=vu[j*33+((h*8+b)^((j>>2)&7))];
            float v0,v1,v2,v3;upk2(vv.x,v0,v1);upk2(vv.y,v2,v3);
            u64 vd0=pk2(v0,v0),vd1=pk2(v1,v1),vd2=pk2(v2,v2),vd3=pk2(v3,v3);
            fma2(o_[0][0],pA.x,vd0);fma2(o_[0][1],pA.x,vd1);fma2(o_[0][2],pA.x,vd2);fma2(o_[0][3],pA.x,vd3);
            fma2(o_[1][0],pA.y,vd0);fma2(o_[1][1],pA.y,vd1);fma2(o_[1][2],pA.y,vd2);fma2(o_[1][3],pA.y,vd3);
            fma2(o_[2][0],pB.x,vd0);fma2(o_[2][1],pB.x,vd1);fma2(o_[2][2],pB.x,vd2);fma2(o_[2][3],pB.x,vd3);
            fma2(o_[3][0],pB.y,vd0);fma2(o_[3][1],pB.y,vd1);fma2(o_[3][2],pB.y,vd2);fma2(o_[3][3],pB.y,vd3);
        }
        __syncthreads();
        #pragma unroll
        for(int ip=0;ip<4;ip++){
            float oa[4],ob[4];
            upk2(o_[ip][0],oa[0],ob[0]);upk2(o_[ip][1],oa[1],ob[1]);
            upk2(o_[ip][2],oa[2],ob[2]);upk2(o_[ip][3],oa[3],ob[3]);
            float ia=inv[ip*2],ib=inv[ip*2+1];
            int iA=i0+ip*2;
            *(float4*)(outsf+iA*132+(h*8+b)*4)=make_float4(oa[0]*ia,oa[1]*ia,oa[2]*ia,oa[3]*ia);
            *(float4*)(outsf+(iA+1)*132+(h*8+b)*4)=make_float4(ob[0]*ib,ob[1]*ib,ob[2]*ib,ob[3]*ib);
        }
    }
    #pragma unroll
    for(int k=0;k<8;k++){
        int f=k*256+tid;
        ps4[(f>>5)*33+(f&31)]=*((const float4*)g_P+f);
    }
    __syncthreads();
    // Phase 4: proj + residual
    {
        u64 acc2[4][4];
        #pragma unroll
        for(int r=0;r<4;r++)
            #pragma unroll
            for(int m=0;m<4;m++)acc2[r][m]=0ull;
        #pragma unroll 4
        for(int k4=0;k4<32;k4++){
            ulonglong2 pr[4],ov[4];
            #pragma unroll
            for(int r=0;r<4;r++)pr[r]=psu[(ty*4+r)*33+k4];
            #pragma unroll
            for(int m=0;m<4;m++)ov[m]=outsu[(m*16+tx)*33+k4];
            #pragma unroll
            for(int r=0;r<4;r++)
                #pragma unroll
                for(int m=0;m<4;m++){fma2(acc2[r][m],pr[r].x,ov[m].x);fma2(acc2[r][m],pr[r].y,ov[m].y);}
        }
        int dy=tx>>2,dx=tx&3;
        #pragma unroll
        for(int r=0;r<4;r++){
            int c=ty*4+r;float pb=g_PB[c];
            #pragma unroll
            for(int m=0;m<4;m++){
                int t=m*16+tx;float lo,hi;upk2(acc2[r][m],lo,hi);
                out[(size_t)c*VOL+base+m*4096+dy*64+dx]=(lo+hi)+pb+sm[c*68+t];
            }
        }
    }
}

extern "C" void kernel_launch(void* const* d_in,const int* in_sizes,int n_in,void* d_out,int out_size){
    cudaFuncSetAttribute(fused_attn_kernel,cudaFuncAttributeMaxDynamicSharedMemorySize,183296);
    prep_kernel<<<290,256>>>((const float*)d_in[2],(const float*)d_in[3],(const float*)d_in[4],(const float*)d_in[5],
                             (const float*)d_in[6],(const float*)d_in[7],(const float*)d_in[8],(const float*)d_in[9],
                             (const float*)d_in[10],(const int*)d_in[11]);
    fused_attn_kernel<<<4096,256,183296>>>((const float*)d_in[0],(const float*)d_in[1],(float*)d_out);
}

// round 15
// speedup vs baseline: 2.7042x; 1.5618x over previous
#include <cuda_runtime.h>
#include <cuda_bf16.h>
#include <cstdint>
#define VOL 262144
typedef unsigned int u32;

__device__ __forceinline__ u32 s2u(const void*p){u32 a;asm("{ .reg .u64 t; cvta.to.shared.u64 t,%1; cvt.u32.u64 %0,t; }":"=r"(a):"l"(p));return a;}
__device__ __forceinline__ u32 bfp(float lo,float hi){u32 r;asm("cvt.rn.satfinite.bf16x2.f32 %0,%1,%2;":"=r"(r):"f"(hi),"f"(lo));return r;}
#define LDSM4(r0,r1,r2,r3,ad) asm volatile("ldmatrix.sync.aligned.m8n8.x4.shared.b16 {%0,%1,%2,%3},[%4];":"=r"(r0),"=r"(r1),"=r"(r2),"=r"(r3):"r"(ad))
#define MMA(c,a0,a1,a2,a3,b0,b1) asm volatile("mma.sync.aligned.m16n8k16.row.col.f32.bf16.bf16.f32 {%0,%1,%2,%3},{%4,%5,%6,%7},{%8,%9},{%0,%1,%2,%3};":"+f"((c)[0]),"+f"((c)[1]),"+f"((c)[2]),"+f"((c)[3]):"r"(a0),"r"(a1),"r"(a2),"r"(a3),"r"(b0),"r"(b1))

__device__ __align__(16) __nv_bfloat16 g_WBF16[3*16384]; // qkv W [o][c] 256B rows, xor (o&7)<<4
__device__ __align__(16) __nv_bfloat16 g_PWB[64*128];    // proj W [c][k] 256B rows, xor (c&7)<<4
__device__ __align__(16) float g_QB[384];
__device__ __align__(16) float g_PB[64];
__device__ __align__(16) float g_BIAS[4*64*64];

__global__ void prep_kernel(const float* __restrict__ conv_w,const float* __restrict__ conv_b,
    const float* __restrict__ trans_w,const float* __restrict__ trans_b,
    const float* __restrict__ qkv_w,const float* __restrict__ qkv_b,
    const float* __restrict__ proj_w,const float* __restrict__ proj_b,
    const float* __restrict__ table,const int* __restrict__ ridx){
    const float SCALE=0.17677669529663688f;
    int id=blockIdx.x*blockDim.x+threadIdx.x;
    if(id<49152){
        int c=id/384,o=id%384;float s=0.f;
        if(c<64){const float*qw=qkv_w+o*128;
            #pragma unroll 8
            for(int m=0;m<64;m++)s+=qw[m]*conv_w[m*64+c];
        }else{const float*qw=qkv_w+o*128+64;int cc=c-64;
            #pragma unroll 8
            for(int m=0;m<64;m++)s+=qw[m]*trans_w[m*64+cc];}
        if(o<128)s*=SCALE;
        int ch=o>>7,ol=o&127;
        u32 byte=(u32)ol*256u+(((u32)c*2u)^(((u32)ol&7u)<<4));
        g_WBF16[ch*16384+(byte>>1)]=__float2bfloat16(s);
    }else if(id<49536){
        int o=id-49152;float s=qkv_b[o];const float*qw=qkv_w+o*128;
        #pragma unroll 8
        for(int m=0;m<64;m++)s+=qw[m]*conv_b[m]+qw[64+m]*trans_b[m];
        if(o<128)s*=SCALE;g_QB[o]=s;
    }else if(id<57728){
        int p=id-49536;int c=p>>7,k=p&127;
        float s=proj_w[c*128+k]+proj_w[(c+64)*128+k];
        u32 byte=(u32)c*256u+(((u32)k*2u)^(((u32)c&7u)<<4));
        g_PWB[byte>>1]=__float2bfloat16(s);
    }else if(id<57792){int c=id-57728;g_PB[c]=proj_b[c]+proj_b[c+64];
    }else if(id<74176){int x=id-57792;int h=x>>12,ij=x&4095;g_BIAS[x]=table[ridx[ij]*4+h];}
}

// smem bytes: feat fp32 [128][68] @0..34816 (fout overlays rows>=64 @17408);
// featB bf16 @40960 (16KB); qTok @57344; kTok @73728; vDim @90112 (128B rows);
// WBuf @106496 (32KB); outsB @139264 (16KB). total 155648 B.
__global__ void __launch_bounds__(256,1)
fused_attn_kernel(const float* __restrict__ conv_feat,const float* __restrict__ trans_feat,float* __restrict__ out){
    extern __shared__ float sm[];
    char* smc=(char*)sm;
    float4* feat4=(float4*)sm;
    const int tid=threadIdx.x, wid=tid>>5, lane=tid&31;
    const int wb=blockIdx.x;
    const int base=((wb>>8)*4)*4096+(((wb>>4)&15)*4)*64+(wb&15)*4;
    const u32 sb=s2u(sm);
    const u32 fB=sb+40960u,qB=sb+57344u,kTB=sb+73728u,vB=sb+90112u,wBs=sb+106496u,oBs=sb+139264u;

    // Phase 1: window load, channel-major fp32
    #pragma unroll
    for(int k=0;k<8;k++){
        int v=k*256+tid, vv=v&1023, c=vv>>4, r16=vv&15;
        const float* src=(v<1024)?conv_feat:trans_feat;
        float4 val=*(const float4*)(src+(size_t)c*VOL+base+(r16>>2)*4096+(r16&3)*64);
        feat4[((v<1024)?c:(64+c))*17+r16]=val;
    }
    __syncthreads();
    // featB bf16 [t][c] 256B rows, xor (t&7)<<4
    #pragma unroll
    for(int i=0;i<16;i++){
        int p=i*256+tid; int t=p&63, c=(p>>6)*2;
        u32 bb=bfp(sm[c*68+t],sm[(c+1)*68+t]);
        u32 byte=(u32)t*256u+(((u32)c*2u)^(((u32)t&7u)<<4));
        *(u32*)(smc+40960+byte)=bb;
    }

    // Phase 2: qkv = featB x W^T  (A=feat tokens M=64, B=weights N=128/chunk)
    const uint4* wsrc=(const uint4*)g_WBF16;
    uint4* wdst=(uint4*)(smc+106496);
    const int mt2=wid>>1, nh=wid&1;
    for(int ch=0;ch<3;ch++){
        #pragma unroll
        for(int i=0;i<8;i++) wdst[i*256+tid]=wsrc[ch*2048+i*256+tid];
        __syncthreads();
        float acc[8][4];
        #pragma unroll
        for(int p=0;p<8;p++){acc[p][0]=0;acc[p][1]=0;acc[p][2]=0;acc[p][3]=0;}
        #pragma unroll
        for(int kc=0;kc<8;kc++){
            u32 t=mt2*16+(lane&15);
            u32 a0,a1,a2,a3; LDSM4(a0,a1,a2,a3,fB+t*256u+(((u32)kc*32u+(((u32)lane>>4)<<4))^((t&7u)<<4)));
            int g=lane>>3;
            #pragma unroll
            for(int p=0;p<4;p++){
                u32 o=nh*64+(2*p+(g>>1))*8+(lane&7);
                u32 b0,b1,b2,b3; LDSM4(b0,b1,b2,b3,wBs+o*256u+(((u32)kc*32u+(((u32)g&1u)<<4))^((o&7u)<<4)));
                MMA(acc[2*p],a0,a1,a2,a3,b0,b1); MMA(acc[2*p+1],a0,a1,a2,a3,b2,b3);
            }
        }
        int r0=mt2*16+(lane>>2), r1=r0+8;
        #pragma unroll
        for(int p=0;p<8;p++){
            int o=nh*64+p*8+(lane&3)*2;
            float2 qb=*(const float2*)(g_QB+ch*128+o);
            float v00=acc[p][0]+qb.x,v01=acc[p][1]+qb.y,v10=acc[p][2]+qb.x,v11=acc[p][3]+qb.y;
            if(ch<2){
                int rb=ch?73728:57344;
                *(u32*)(smc+rb+(u32)r0*256u+(((u32)o*2u)^((r0&7u)<<4)))=bfp(v00,v01);
                *(u32*)(smc+rb+(u32)r1*256u+(((u32)o*2u)^((r1&7u)<<4)))=bfp(v10,v11);
            }else{
                *(__nv_bfloat16*)(smc+90112+(u32)o*128u+(((u32)r0*2u)^((o&7u)<<4)))=__float2bfloat16(v00);
                *(__nv_bfloat16*)(smc+90112+(u32)(o+1)*128u+(((u32)r0*2u)^(((o+1)&7u)<<4)))=__float2bfloat16(v01);
                *(__nv_bfloat16*)(smc+90112+(u32)o*128u+(((u32)r1*2u)^((o&7u)<<4)))=__float2bfloat16(v10);
                *(__nv_bfloat16*)(smc+90112+(u32)(o+1)*128u+(((u32)r1*2u)^(((o+1)&7u)<<4)))=__float2bfloat16(v11);
            }
        }
        __syncthreads();
    }
    // stage proj weights into WBuf (qkv-weight reads finished at the sync above)
    #pragma unroll
    for(int i=0;i<4;i++) wdst[i*256+tid]=((const uint4*)g_PWB)[i*256+tid];

    // Phase 3: attention. warp: head h = wid>>1, row-half mh = wid&1
    const int h=wid>>1, mh=wid&1;
    float sacc[2][8][4];
    #pragma unroll
    for(int mt=0;mt<2;mt++)
        #pragma unroll
        for(int nt=0;nt<8;nt++){
            int i0=mh*32+mt*16+(lane>>2), j=nt*8+(lane&3)*2;
            float2 b0=*(const float2*)(g_BIAS+h*4096+i0*64+j);
            float2 b1=*(const float2*)(g_BIAS+h*4096+(i0+8)*64+j);
            sacc[mt][nt][0]=b0.x;sacc[mt][nt][1]=b0.y;sacc[mt][nt][2]=b1.x;sacc[mt][nt][3]=b1.y;
        }
    #pragma unroll
    for(int kc=0;kc<2;kc++){
        u32 kbase=(u32)h*64u+(u32)kc*32u;
        u32 a[2][4];
        #pragma unroll
        for(int mt=0;mt<2;mt++){
            u32 t=mh*32+mt*16+(lane&15);
            LDSM4(a[mt][0],a[mt][1],a[mt][2],a[mt][3],qB+t*256u+((kbase+(((u32)lane>>4)<<4))^((t&7u)<<4)));
        }
        int g=lane>>3;
        #pragma unroll
        for(int p=0;p<4;p++){
            u32 j=(2*p+(g>>1))*8+(lane&7);
            u32 b0,b1,b2,b3; LDSM4(b0,b1,b2,b3,kTB+j*256u+((kbase+(((u32)g&1u)<<4))^((j&7u)<<4)));
            #pragma unroll
            for(int mt=0;mt<2;mt++){
                MMA(sacc[mt][2*p],a[mt][0],a[mt][1],a[mt][2],a[mt][3],b0,b1);
                MMA(sacc[mt][2*p+1],a[mt][0],a[mt][1],a[mt][2],a[mt][3],b2,b3);
            }
        }
    }
    float inv[2][2];
    #pragma unroll
    for(int mt=0;mt<2;mt++)
        #pragma unroll
        for(int hf=0;hf<2;hf++){
            float m=-1e30f;
            #pragma unroll
            for(int nt=0;nt<8;nt++){m=fmaxf(m,sacc[mt][nt][hf*2]);m=fmaxf(m,sacc[mt][nt][hf*2+1]);}
            m=fmaxf(m,__shfl_xor_sync(~0u,m,1)); m=fmaxf(m,__shfl_xor_sync(~0u,m,2));
            float s=0.f;
            #pragma unroll
            for(int nt=0;nt<8;nt++){
                float e0=__expf(sacc[mt][nt][hf*2]-m), e1=__expf(sacc[mt][nt][hf*2+1]-m);
                sacc[mt][nt][hf*2]=e0; sacc[mt][nt][hf*2+1]=e1; s+=e0+e1;
            }
            s+=__shfl_xor_sync(~0u,s,1); s+=__shfl_xor_sync(~0u,s,2);
            inv[mt][hf]=1.f/s;
        }
    float oacc[2][4][4];
    #pragma unroll
    for(int mt=0;mt<2;mt++)
        #pragma unroll
        for(int p=0;p<4;p++){oacc[mt][p][0]=0;oacc[mt][p][1]=0;oacc[mt][p][2]=0;oacc[mt][p][3]=0;}
    #pragma unroll
    for(int ks=0;ks<4;ks++){
        u32 pa[2][4];
        #pragma unroll
        for(int mt=0;mt<2;mt++){
            pa[mt][0]=bfp(sacc[mt][2*ks][0],sacc[mt][2*ks][1]);
            pa[mt][1]=bfp(sacc[mt][2*ks][2],sacc[mt][2*ks][3]);
            pa[mt][2]=bfp(sacc[mt][2*ks+1][0],sacc[mt][2*ks+1][1]);
            pa[mt][3]=bfp(sacc[mt][2*ks+1][2],sacc[mt][2*ks+1][3]);
        }
        int g=lane>>3;
        #pragma unroll
        for(int p2=0;p2<2;p2++){
            u32 dv=h*32+(2*p2+(g>>1))*8+(lane&7);
            u32 b0,b1,b2,b3; LDSM4(b0,b1,b2,b3,vB+dv*128u+(((u32)ks*32u+(((u32)g&1u)<<4))^((dv&7u)<<4)));
            #pragma unroll
            for(int mt=0;mt<2;mt++){
                MMA(oacc[mt][2*p2],pa[mt][0],pa[mt][1],pa[mt][2],pa[mt][3],b0,b1);
                MMA(oacc[mt][2*p2+1],pa[mt][0],pa[mt][1],pa[mt][2],pa[mt][3],b2,b3);
            }
        }
    }
    #pragma unroll
    for(int mt=0;mt<2;mt++){
        int r0=mh*32+mt*16+(lane>>2), r1=r0+8;
        #pragma unroll
        for(int p=0;p<4;p++){
            int ko=h*32+p*8+(lane&3)*2;
            *(u32*)(smc+139264+(u32)r0*256u+(((u32)ko*2u)^((r0&7u)<<4)))=bfp(oacc[mt][p][0]*inv[mt][0],oacc[mt][p][1]*inv[mt][0]);
            *(u32*)(smc+139264+(u32)r1*256u+(((u32)ko*2u)^((r1&7u)<<4)))=bfp(oacc[mt][p][2]*inv[mt][1],oacc[mt][p][3]*inv[mt][1]);
        }
    }
    __syncthreads();

    // Phase 4: proj (A=outsB tokens, B=PW) + PB -> fout, then residual + store
    {
        const int mt4=wid>>1, nh4=wid&1;
        float pacc[4][4];
        #pragma unroll
        for(int p=0;p<4;p++){pacc[p][0]=0;pacc[p][1]=0;pacc[p][2]=0;pacc[p][3]=0;}
        #pragma unroll
        for(int kc=0;kc<8;kc++){
            u32 t=mt4*16+(lane&15);
            u32 a0,a1,a2,a3; LDSM4(a0,a1,a2,a3,oBs+t*256u+(((u32)kc*32u+(((u32)lane>>4)<<4))^((t&7u)<<4)));
            int g=lane>>3;
            #pragma unroll
            for(int p2=0;p2<2;p2++){
                u32 c=nh4*32+(2*p2+(g>>1))*8+(lane&7);
                u32 b0,b1,b2,b3; LDSM4(b0,b1,b2,b3,wBs+c*256u+(((u32)kc*32u+(((u32)g&1u)<<4))^((c&7u)<<4)));
                MMA(pacc[2*p2],a0,a1,a2,a3,b0,b1); MMA(pacc[2*p2+1],a0,a1,a2,a3,b2,b3);
            }
        }
        float* fout=sm+4352;
        int r0=mt4*16+(lane>>2), r1=r0+8;
        #pragma unroll
        for(int p=0;p<4;p++){
            int c=nh4*32+p*8+(lane&3)*2;
            float2 pb=*(const float2*)(g_PB+c);
            fout[r0*68+c]=pacc[p][0]+pb.x; fout[r0*68+c+1]=pacc[p][1]+pb.y;
            fout[r1*68+c]=pacc[p][2]+pb.x; fout[r1*68+c+1]=pacc[p][3]+pb.y;
        }
    }
    __syncthreads();
    {
        const float* fout=sm+4352;
        int tx=tid&15, ty=tid>>4, dy=tx>>2, dx=tx&3;
        #pragma unroll
        for(int r=0;r<4;r++){
            int c=ty*4+r;
            #pragma unroll
            for(int m=0;m<4;m++){
                int t=m*16+tx;
                out[(size_t)c*VOL+base+m*4096+dy*64+dx]=fout[t*68+c]+sm[c*68+t];
            }
        }
    }
}

extern "C" void kernel_launch(void* const* d_in,const int* in_sizes,int n_in,void* d_out,int out_size){
    cudaFuncSetAttribute(fused_attn_kernel,cudaFuncAttributeMaxDynamicSharedMemorySize,155648);
    prep_kernel<<<290,256>>>((const float*)d_in[2],(const float*)d_in[3],(const float*)d_in[4],(const float*)d_in[5],
                             (const float*)d_in[6],(const float*)d_in[7],(const float*)d_in[8],(const float*)d_in[9],
                             (const float*)d_in[10],(const int*)d_in[11]);
    fused_attn_kernel<<<4096,256,155648>>>((const float*)d_in[0],(const float*)d_in[1],(float*)d_out);
}

// round 16
// speedup vs baseline: 3.1386x; 1.1607x over previous
#include <cuda_runtime.h>
#include <cuda_bf16.h>
#include <cstdint>
#define VOL 262144
typedef unsigned int u32;

__device__ __forceinline__ u32 s2u(const void*p){u32 a;asm("{ .reg .u64 t; cvta.to.shared.u64 t,%1; cvt.u32.u64 %0,t; }":"=r"(a):"l"(p));return a;}
__device__ __forceinline__ u32 bfp(float lo,float hi){u32 r;asm("cvt.rn.satfinite.bf16x2.f32 %0,%1,%2;":"=r"(r):"f"(hi),"f"(lo));return r;}
#define LDSM4(r0,r1,r2,r3,ad) asm volatile("ldmatrix.sync.aligned.m8n8.x4.shared.b16 {%0,%1,%2,%3},[%4];":"=r"(r0),"=r"(r1),"=r"(r2),"=r"(r3):"r"(ad))
#define MMA(c,a0,a1,a2,a3,b0,b1) asm volatile("mma.sync.aligned.m16n8k16.row.col.f32.bf16.bf16.f32 {%0,%1,%2,%3},{%4,%5,%6,%7},{%8,%9},{%0,%1,%2,%3};":"+f"((c)[0]),"+f"((c)[1]),"+f"((c)[2]),"+f"((c)[3]):"r"(a0),"r"(a1),"r"(a2),"r"(a3),"r"(b0),"r"(b1))

__device__ __align__(16) __nv_bfloat16 g_WBF16[3*16384]; // qkv W [o][c] 256B rows, xor (o&7)<<4
__device__ __align__(16) __nv_bfloat16 g_PWB[64*128];    // proj W [c][k] 256B rows, xor (c&7)<<4
__device__ __align__(16) float g_QB[384];
__device__ __align__(16) float g_PB[64];
__device__ __align__(16) float g_BIAS[4*64*64];

__global__ void prep_kernel(const float* __restrict__ conv_w,const float* __restrict__ conv_b,
    const float* __restrict__ trans_w,const float* __restrict__ trans_b,
    const float* __restrict__ qkv_w,const float* __restrict__ qkv_b,
    const float* __restrict__ proj_w,const float* __restrict__ proj_b,
    const float* __restrict__ table,const int* __restrict__ ridx){
    const float SCALE=0.17677669529663688f;
    int id=blockIdx.x*blockDim.x+threadIdx.x;
    if(id<49152){
        int c=id/384,o=id%384;float s=0.f;
        if(c<64){const float*qw=qkv_w+o*128;
            #pragma unroll 8
            for(int m=0;m<64;m++)s+=qw[m]*conv_w[m*64+c];
        }else{const float*qw=qkv_w+o*128+64;int cc=c-64;
            #pragma unroll 8
            for(int m=0;m<64;m++)s+=qw[m]*trans_w[m*64+cc];}
        if(o<128)s*=SCALE;
        int ch=o>>7,ol=o&127;
        u32 byte=(u32)ol*256u+(((u32)c*2u)^(((u32)ol&7u)<<4));
        g_WBF16[ch*16384+(byte>>1)]=__float2bfloat16(s);
    }else if(id<49536){
        int o=id-49152;float s=qkv_b[o];const float*qw=qkv_w+o*128;
        #pragma unroll 8
        for(int m=0;m<64;m++)s+=qw[m]*conv_b[m]+qw[64+m]*trans_b[m];
        if(o<128)s*=SCALE;g_QB[o]=s;
    }else if(id<57728){
        int p=id-49536;int c=p>>7,k=p&127;
        float s=proj_w[c*128+k]+proj_w[(c+64)*128+k];
        u32 byte=(u32)c*256u+(((u32)k*2u)^(((u32)c&7u)<<4));
        g_PWB[byte>>1]=__float2bfloat16(s);
    }else if(id<57792){int c=id-57728;g_PB[c]=proj_b[c]+proj_b[c+64];
    }else if(id<74176){int x=id-57792;int h=x>>12,ij=x&4095;g_BIAS[x]=table[ridx[ij]*4+h];}
}

// smem bytes (total 98304, 2 CTAs/SM):
//   featB bf16 @0 (16K)   [outsB overlays @0 after phase 2]
//   qTok @16384 (16K)     [fout fp32 [64][68] overlays @16384 after phase 3]
//   kTok @32768 (16K)
//   vDim @49152 (16K, 128B rows)   [feat fp32 temp @49152..84000 during phase 1 only]
//   WBuf @65536 (32K)
__global__ void __launch_bounds__(256,2)
fused_attn_kernel(const float* __restrict__ conv_feat,const float* __restrict__ trans_feat,float* __restrict__ out){
    extern __shared__ float sm[];
    char* smc=(char*)sm;
    const int tid=threadIdx.x, wid=tid>>5, lane=tid&31;
    const int wb=blockIdx.x;
    const int base=((wb>>8)*4)*4096+(((wb>>4)&15)*4)*64+(wb&15)*4;
    const u32 sb=s2u(sm);
    const u32 fB=sb+0u,qB=sb+16384u,kTB=sb+32768u,vB=sb+49152u,wBs=sb+65536u,oBs=sb+0u;
    float* ftf=(float*)(smc+49152);          // fp32 feat temp [128][68]
    float4* ft4=(float4*)(smc+49152);

    // Phase 1: window load, channel-major fp32 (temp region)
    #pragma unroll
    for(int k=0;k<8;k++){
        int v=k*256+tid, vv=v&1023, c=vv>>4, r16=vv&15;
        const float* src=(v<1024)?conv_feat:trans_feat;
        float4 val=*(const float4*)(src+(size_t)c*VOL+base+(r16>>2)*4096+(r16&3)*64);
        ft4[((v<1024)?c:(64+c))*17+r16]=val;
    }
    __syncthreads();
    // featB bf16 [t][c] 256B rows, xor (t&7)<<4
    #pragma unroll
    for(int i=0;i<16;i++){
        int p=i*256+tid; int t=p&63, c=(p>>6)*2;
        u32 bb=bfp(ftf[c*68+t],ftf[(c+1)*68+t]);
        u32 byte=(u32)t*256u+(((u32)c*2u)^(((u32)t&7u)<<4));
        *(u32*)(smc+0+byte)=bb;
    }
    __syncthreads();   // feat temp dead; WBuf/vDim free for reuse

    // Phase 2: qkv = featB x W^T  (A=feat tokens M=64, B=weights N=128/chunk)
    const uint4* wsrc=(const uint4*)g_WBF16;
    uint4* wdst=(uint4*)(smc+65536);
    const int mt2=wid>>1, nh=wid&1;
    for(int ch=0;ch<3;ch++){
        #pragma unroll
        for(int i=0;i<8;i++) wdst[i*256+tid]=wsrc[ch*2048+i*256+tid];
        __syncthreads();
        float acc[8][4];
        #pragma unroll
        for(int p=0;p<8;p++){acc[p][0]=0;acc[p][1]=0;acc[p][2]=0;acc[p][3]=0;}
        #pragma unroll
        for(int kc=0;kc<8;kc++){
            u32 t=mt2*16+(lane&15);
            u32 a0,a1,a2,a3; LDSM4(a0,a1,a2,a3,fB+t*256u+(((u32)kc*32u+(((u32)lane>>4)<<4))^((t&7u)<<4)));
            int g=lane>>3;
            #pragma unroll
            for(int p=0;p<4;p++){
                u32 o=nh*64+(2*p+(g>>1))*8+(lane&7);
                u32 b0,b1,b2,b3; LDSM4(b0,b1,b2,b3,wBs+o*256u+(((u32)kc*32u+(((u32)g&1u)<<4))^((o&7u)<<4)));
                MMA(acc[2*p],a0,a1,a2,a3,b0,b1); MMA(acc[2*p+1],a0,a1,a2,a3,b2,b3);
            }
        }
        int r0=mt2*16+(lane>>2), r1=r0+8;
        #pragma unroll
        for(int p=0;p<8;p++){
            int o=nh*64+p*8+(lane&3)*2;
            float2 qb=*(const float2*)(g_QB+ch*128+o);
            float v00=acc[p][0]+qb.x,v01=acc[p][1]+qb.y,v10=acc[p][2]+qb.x,v11=acc[p][3]+qb.y;
            if(ch<2){
                int rb=ch?32768:16384;
                *(u32*)(smc+rb+(u32)r0*256u+(((u32)o*2u)^((r0&7u)<<4)))=bfp(v00,v01);
                *(u32*)(smc+rb+(u32)r1*256u+(((u32)o*2u)^((r1&7u)<<4)))=bfp(v10,v11);
            }else{
                *(__nv_bfloat16*)(smc+49152+(u32)o*128u+(((u32)r0*2u)^((o&7u)<<4)))=__float2bfloat16(v00);
                *(__nv_bfloat16*)(smc+49152+(u32)(o+1)*128u+(((u32)r0*2u)^(((o+1)&7u)<<4)))=__float2bfloat16(v01);
                *(__nv_bfloat16*)(smc+49152+(u32)o*128u+(((u32)r1*2u)^((o&7u)<<4)))=__float2bfloat16(v10);
                *(__nv_bfloat16*)(smc+49152+(u32)(o+1)*128u+(((u32)r1*2u)^(((o+1)&7u)<<4)))=__float2bfloat16(v11);
            }
        }
        __syncthreads();
    }
    // stage proj weights into WBuf (qkv-weight reads done at the sync above)
    #pragma unroll
    for(int i=0;i<4;i++) wdst[i*256+tid]=((const uint4*)g_PWB)[i*256+tid];

    // Phase 3: attention. warp: head h = wid>>1, row-half mh = wid&1
    const int h=wid>>1, mh=wid&1;
    float sacc[2][8][4];
    #pragma unroll
    for(int mt=0;mt<2;mt++)
        #pragma unroll
        for(int nt=0;nt<8;nt++){
            int i0=mh*32+mt*16+(lane>>2), j=nt*8+(lane&3)*2;
            float2 b0=*(const float2*)(g_BIAS+h*4096+i0*64+j);
            float2 b1=*(const float2*)(g_BIAS+h*4096+(i0+8)*64+j);
            sacc[mt][nt][0]=b0.x;sacc[mt][nt][1]=b0.y;sacc[mt][nt][2]=b1.x;sacc[mt][nt][3]=b1.y;
        }
    #pragma unroll
    for(int kc=0;kc<2;kc++){
        u32 kbase=(u32)h*64u+(u32)kc*32u;
        u32 a[2][4];
        #pragma unroll
        for(int mt=0;mt<2;mt++){
            u32 t=mh*32+mt*16+(lane&15);
            LDSM4(a[mt][0],a[mt][1],a[mt][2],a[mt][3],qB+t*256u+((kbase+(((u32)lane>>4)<<4))^((t&7u)<<4)));
        }
        int g=lane>>3;
        #pragma unroll
        for(int p=0;p<4;p++){
            u32 j=(2*p+(g>>1))*8+(lane&7);
            u32 b0,b1,b2,b3; LDSM4(b0,b1,b2,b3,kTB+j*256u+((kbase+(((u32)g&1u)<<4))^((j&7u)<<4)));
            #pragma unroll
            for(int mt=0;mt<2;mt++){
                MMA(sacc[mt][2*p],a[mt][0],a[mt][1],a[mt][2],a[mt][3],b0,b1);
                MMA(sacc[mt][2*p+1],a[mt][0],a[mt][1],a[mt][2],a[mt][3],b2,b3);
            }
        }
    }
    float inv[2][2];
    #pragma unroll
    for(int mt=0;mt<2;mt++)
        #pragma unroll
        for(int hf=0;hf<2;hf++){
            float m=-1e30f;
            #pragma unroll
            for(int nt=0;nt<8;nt++){m=fmaxf(m,sacc[mt][nt][hf*2]);m=fmaxf(m,sacc[mt][nt][hf*2+1]);}
            m=fmaxf(m,__shfl_xor_sync(~0u,m,1)); m=fmaxf(m,__shfl_xor_sync(~0u,m,2));
            float s=0.f;
            #pragma unroll
            for(int nt=0;nt<8;nt++){
                float e0=__expf(sacc[mt][nt][hf*2]-m), e1=__expf(sacc[mt][nt][hf*2+1]-m);
                sacc[mt][nt][hf*2]=e0; sacc[mt][nt][hf*2+1]=e1; s+=e0+e1;
            }
            s+=__shfl_xor_sync(~0u,s,1); s+=__shfl_xor_sync(~0u,s,2);
            inv[mt][hf]=1.f/s;
        }
    float oacc[2][4][4];
    #pragma unroll
    for(int mt=0;mt<2;mt++)
        #pragma unroll
        for(int p=0;p<4;p++){oacc[mt][p][0]=0;oacc[mt][p][1]=0;oacc[mt][p][2]=0;oacc[mt][p][3]=0;}
    #pragma unroll
    for(int ks=0;ks<4;ks++){
        u32 pa[2][4];
        #pragma unroll
        for(int mt=0;mt<2;mt++){
            pa[mt][0]=bfp(sacc[mt][2*ks][0],sacc[mt][2*ks][1]);
            pa[mt][1]=bfp(sacc[mt][2*ks][2],sacc[mt][2*ks][3]);
            pa[mt][2]=bfp(sacc[mt][2*ks+1][0],sacc[mt][2*ks+1][1]);
            pa[mt][3]=bfp(sacc[mt][2*ks+1][2],sacc[mt][2*ks+1][3]);
        }
        int g=lane>>3;
        #pragma unroll
        for(int p2=0;p2<2;p2++){
            u32 dv=h*32+(2*p2+(g>>1))*8+(lane&7);
            u32 b0,b1,b2,b3; LDSM4(b0,b1,b2,b3,vB+dv*128u+(((u32)ks*32u+(((u32)g&1u)<<4))^((dv&7u)<<4)));
            #pragma unroll
            for(int mt=0;mt<2;mt++){
                MMA(oacc[mt][2*p2],pa[mt][0],pa[mt][1],pa[mt][2],pa[mt][3],b0,b1);
                MMA(oacc[mt][2*p2+1],pa[mt][0],pa[mt][1],pa[mt][2],pa[mt][3],b2,b3);
            }
        }
    }
    __syncthreads();   // featB reads done; outsB may overwrite @0
    #pragma unroll
    for(int mt=0;mt<2;mt++){
        int r0=mh*32+mt*16+(lane>>2), r1=r0+8;
        #pragma unroll
        for(int p=0;p<4;p++){
            int ko=h*32+p*8+(lane&3)*2;
            *(u32*)(smc+0+(u32)r0*256u+(((u32)ko*2u)^((r0&7u)<<4)))=bfp(oacc[mt][p][0]*inv[mt][0],oacc[mt][p][1]*inv[mt][0]);
            *(u32*)(smc+0+(u32)r1*256u+(((u32)ko*2u)^((r1&7u)<<4)))=bfp(oacc[mt][p][2]*inv[mt][1],oacc[mt][p][3]*inv[mt][1]);
        }
    }
    __syncthreads();

    // Phase 4: proj (A=outsB tokens, B=PW) + PB -> fout, then residual(gmem) + store
    {
        const int mt4=wid>>1, nh4=wid&1;
        float pacc[4][4];
        #pragma unroll
        for(int p=0;p<4;p++){pacc[p][0]=0;pacc[p][1]=0;pacc[p][2]=0;pacc[p][3]=0;}
        #pragma unroll
        for(int kc=0;kc<8;kc++){
            u32 t=mt4*16+(lane&15);
            u32 a0,a1,a2,a3; LDSM4(a0,a1,a2,a3,oBs+t*256u+(((u32)kc*32u+(((u32)lane>>4)<<4))^((t&7u)<<4)));
            int g=lane>>3;
            #pragma unroll
            for(int p2=0;p2<2;p2++){
                u32 c=nh4*32+(2*p2+(g>>1))*8+(lane&7);
                u32 b0,b1,b2,b3; LDSM4(b0,b1,b2,b3,wBs+c*256u+(((u32)kc*32u+(((u32)g&1u)<<4))^((c&7u)<<4)));
                MMA(pacc[2*p2],a0,a1,a2,a3,b0,b1); MMA(pacc[2*p2+1],a0,a1,a2,a3,b2,b3);
            }
        }
        float* fout=(float*)(smc+16384);
        int r0=mt4*16+(lane>>2), r1=r0+8;
        #pragma unroll
        for(int p=0;p<4;p++){
            int c=nh4*32+p*8+(lane&3)*2;
            float2 pb=*(const float2*)(g_PB+c);
            fout[r0*68+c]=pacc[p][0]+pb.x; fout[r0*68+c+1]=pacc[p][1]+pb.y;
            fout[r1*68+c]=pacc[p][2]+pb.x; fout[r1*68+c+1]=pacc[p][3]+pb.y;
        }
    }
    __syncthreads();
    {
        const float* fout=(const float*)(smc+16384);
        int tx=tid&15, ty=tid>>4, dy=tx>>2, dx=tx&3;
        #pragma unroll
        for(int r=0;r<4;r++){
            int c=ty*4+r;
            #pragma unroll
            for(int m=0;m<4;m++){
                int t=m*16+tx;
                size_t gi=(size_t)c*VOL+base+m*4096+dy*64+dx;
                out[gi]=fout[t*68+c]+conv_feat[gi];
            }
        }
    }
}

extern "C" void kernel_launch(void* const* d_in,const int* in_sizes,int n_in,void* d_out,int out_size){
    cudaFuncSetAttribute(fused_attn_kernel,cudaFuncAttributeMaxDynamicSharedMemorySize,98304);
    prep_kernel<<<290,256>>>((const float*)d_in[2],(const float*)d_in[3],(const float*)d_in[4],(const float*)d_in[5],
                             (const float*)d_in[6],(const float*)d_in[7],(const float*)d_in[8],(const float*)d_in[9],
                             (const float*)d_in[10],(const int*)d_in[11]);
    fused_attn_kernel<<<4096,256,98304>>>((const float*)d_in[0],(const float*)d_in[1],(float*)d_out);
}

// round 17
// speedup vs baseline: 3.2696x; 1.0417x over previous
#include <cuda_runtime.h>
#include <cuda_bf16.h>
#include <cstdint>
#define VOL 262144
typedef unsigned int u32;

__device__ __forceinline__ u32 s2u(const void*p){u32 a;asm("{ .reg .u64 t; cvta.to.shared.u64 t,%1; cvt.u32.u64 %0,t; }":"=r"(a):"l"(p));return a;}
__device__ __forceinline__ u32 bfp(float lo,float hi){u32 r;asm("cvt.rn.satfinite.bf16x2.f32 %0,%1,%2;":"=r"(r):"f"(hi),"f"(lo));return r;}
#define LDSM4(r0,r1,r2,r3,ad) asm volatile("ldmatrix.sync.aligned.m8n8.x4.shared.b16 {%0,%1,%2,%3},[%4];":"=r"(r0),"=r"(r1),"=r"(r2),"=r"(r3):"r"(ad))
#define LDSM4T(r0,r1,r2,r3,ad) asm volatile("ldmatrix.sync.aligned.m8n8.x4.trans.shared.b16 {%0,%1,%2,%3},[%4];":"=r"(r0),"=r"(r1),"=r"(r2),"=r"(r3):"r"(ad))
#define MMA(c,a0,a1,a2,a3,b0,b1) asm volatile("mma.sync.aligned.m16n8k16.row.col.f32.bf16.bf16.f32 {%0,%1,%2,%3},{%4,%5,%6,%7},{%8,%9},{%0,%1,%2,%3};":"+f"((c)[0]),"+f"((c)[1]),"+f"((c)[2]),"+f"((c)[3]):"r"(a0),"r"(a1),"r"(a2),"r"(a3),"r"(b0),"r"(b1))
#define CPA16(dst,src) asm volatile("cp.async.cg.shared.global [%0],[%1],16;"::"r"(dst),"l"(src):"memory")
#define CPA_COMMIT() asm volatile("cp.async.commit_group;":::"memory")
#define CPA_WAIT1() asm volatile("cp.async.wait_group 1;":::"memory")
#define CPA_WAIT0() asm volatile("cp.async.wait_group 0;":::"memory")

// qkv weights in HALF-CHUNK major: 6 halves of 16KB; half hc=ch*2+(c>=64); inside: [o 0..127] rows of 128B,
// byte = o*128 + ((cl*2) ^ ((o&7)<<4)), cl=c&63.
__device__ __align__(16) __nv_bfloat16 g_WBF16[3*16384];
__device__ __align__(16) __nv_bfloat16 g_PWB[64*128];    // proj W [c][k] 256B rows, xor (c&7)<<4
__device__ __align__(16) float g_QB[384];
__device__ __align__(16) float g_PB[64];
__device__ __align__(16) float g_BIAS[4*64*64];

__global__ void prep_kernel(const float* __restrict__ conv_w,const float* __restrict__ conv_b,
    const float* __restrict__ trans_w,const float* __restrict__ trans_b,
    const float* __restrict__ qkv_w,const float* __restrict__ qkv_b,
    const float* __restrict__ proj_w,const float* __restrict__ proj_b,
    const float* __restrict__ table,const int* __restrict__ ridx){
    const float SCALE=0.17677669529663688f;
    int id=blockIdx.x*blockDim.x+threadIdx.x;
    if(id<49152){
        int c=id/384,o=id%384;float s=0.f;
        if(c<64){const float*qw=qkv_w+o*128;
            #pragma unroll 8
            for(int m=0;m<64;m++)s+=qw[m]*conv_w[m*64+c];
        }else{const float*qw=qkv_w+o*128+64;int cc=c-64;
            #pragma unroll 8
            for(int m=0;m<64;m++)s+=qw[m]*trans_w[m*64+cc];}
        if(o<128)s*=SCALE;
        int ch=o>>7,ol=o&127,hc=ch*2+(c>>6),cl=c&63;
        u32 byte=(u32)hc*16384u+(u32)ol*128u+(((u32)cl*2u)^(((u32)ol&7u)<<4));
        g_WBF16[byte>>1]=__float2bfloat16(s);
    }else if(id<49536){
        int o=id-49152;float s=qkv_b[o];const float*qw=qkv_w+o*128;
        #pragma unroll 8
        for(int m=0;m<64;m++)s+=qw[m]*conv_b[m]+qw[64+m]*trans_b[m];
        if(o<128)s*=SCALE;g_QB[o]=s;
    }else if(id<57728){
        int p=id-49536;int c=p>>7,k=p&127;
        float s=proj_w[c*128+k]+proj_w[(c+64)*128+k];
        u32 byte=(u32)c*256u+(((u32)k*2u)^(((u32)c&7u)<<4));
        g_PWB[byte>>1]=__float2bfloat16(s);
    }else if(id<57792){int c=id-57728;g_PB[c]=proj_b[c]+proj_b[c+64];
    }else if(id<74176){int x=id-57792;int h=x>>12,ij=x&4095;g_BIAS[x]=table[ridx[ij]*4+h];}
}

// smem (98304 B, 2 CTAs/SM):
//   featB bf16 @0 (16K)            [outsB overlays @0 after phase 3]
//   qTok @16384                    [fp32 feat temp @16384..51200 phase1; fout @16384 after phase 3]
//   kTok @32768
//   vTok @49152 (token-major, like kTok; consumed via ldmatrix.trans)
//   wbuf0 @65536 (16K), wbuf1 @81920 (16K)  — cp.async double buffer
__global__ void __launch_bounds__(256,2)
fused_attn_kernel(const float* __restrict__ conv_feat,const float* __restrict__ trans_feat,float* __restrict__ out){
    extern __shared__ float sm[];
    char* smc=(char*)sm;
    const int tid=threadIdx.x, wid=tid>>5, lane=tid&31;
    const int wb=blockIdx.x;
    const int base=((wb>>8)*4)*4096+(((wb>>4)&15)*4)*64+(wb&15)*4;
    const u32 sb=s2u(sm);
    const u32 fB=sb+0u,qB=sb+16384u,kTB=sb+32768u,vB=sb+49152u;
    const u32 wb0=sb+65536u,wb1=sb+81920u;
    const char* gw=(const char*)g_WBF16;

    // prefetch weight halves H0,H1 immediately
    #pragma unroll
    for(int i=0;i<4;i++) CPA16(wb0+(u32)(i*256+tid)*16u,gw+(i*256+tid)*16);
    CPA_COMMIT();
    #pragma unroll
    for(int i=0;i<4;i++) CPA16(wb1+(u32)(i*256+tid)*16u,gw+16384+(i*256+tid)*16);
    CPA_COMMIT();

    // Phase 1: window load -> fp32 temp @16384
    float* ftf=(float*)(smc+16384);
    float4* ft4=(float4*)(smc+16384);
    #pragma unroll
    for(int k=0;k<8;k++){
        int v=k*256+tid, vv=v&1023, c=vv>>4, r16=vv&15;
        const float* src=(v<1024)?conv_feat:trans_feat;
        float4 val=*(const float4*)(src+(size_t)c*VOL+base+(r16>>2)*4096+(r16&3)*64);
        ft4[((v<1024)?c:(64+c))*17+r16]=val;
    }
    __syncthreads();
    // featB bf16 [t][c] 256B rows, xor (t&7)<<4
    #pragma unroll
    for(int i=0;i<16;i++){
        int p=i*256+tid; int t=p&63, c=(p>>6)*2;
        u32 bb=bfp(ftf[c*68+t],ftf[(c+1)*68+t]);
        u32 byte=(u32)t*256u+(((u32)c*2u)^(((u32)t&7u)<<4));
        *(u32*)(smc+0+byte)=bb;
    }

    // Phase 2: qkv = featB x W^T, weights streamed in 16KB halves
    const int mt2=wid>>1, nh=wid&1;
    for(int ch=0;ch<3;ch++){
        float acc[8][4];
        #pragma unroll
        for(int p=0;p<8;p++){acc[p][0]=0;acc[p][1]=0;acc[p][2]=0;acc[p][3]=0;}
        #pragma unroll
        for(int half=0;half<2;half++){
            int hc=ch*2+half;
            CPA_WAIT1();
            __syncthreads();
            u32 wbase=(hc&1)?wb1:wb0;
            #pragma unroll
            for(int kcl=0;kcl<4;kcl++){
                int kc=half*4+kcl;
                u32 t=mt2*16+(lane&15);
                u32 a0,a1,a2,a3; LDSM4(a0,a1,a2,a3,fB+t*256u+(((u32)kc*32u+(((u32)lane>>4)<<4))^((t&7u)<<4)));
                int g=lane>>3;
                #pragma unroll
                for(int p=0;p<4;p++){
                    u32 o=nh*64+(2*p+(g>>1))*8+(lane&7);
                    u32 b0,b1,b2,b3; LDSM4(b0,b1,b2,b3,wbase+o*128u+(((u32)kcl*32u+(((u32)g&1u)<<4))^((o&7u)<<4)));
                    MMA(acc[2*p],a0,a1,a2,a3,b0,b1); MMA(acc[2*p+1],a0,a1,a2,a3,b2,b3);
                }
            }
            __syncthreads();
            if(hc<4){
                u32 dbuf=(hc&1)?wb1:wb0;
                #pragma unroll
                for(int i=0;i<4;i++) CPA16(dbuf+(u32)(i*256+tid)*16u,gw+(hc+2)*16384+(i*256+tid)*16);
                CPA_COMMIT();
            }else if(hc==4){
                #pragma unroll
                for(int i=0;i<4;i++) CPA16(wb0+(u32)(i*256+tid)*16u,(const char*)g_PWB+(i*256+tid)*16);
                CPA_COMMIT();
            }
        }
        // epilogue: bias + store (q/k/v all token-major u32 pairs)
        int r0=mt2*16+(lane>>2), r1=r0+8;
        int rb=(ch==0)?16384:(ch==1)?32768:49152;
        #pragma unroll
        for(int p=0;p<8;p++){
            int o=nh*64+p*8+(lane&3)*2;
            float2 qb=*(const float2*)(g_QB+ch*128+o);
            *(u32*)(smc+rb+(u32)r0*256u+(((u32)o*2u)^((r0&7u)<<4)))=bfp(acc[p][0]+qb.x,acc[p][1]+qb.y);
            *(u32*)(smc+rb+(u32)r1*256u+(((u32)o*2u)^((r1&7u)<<4)))=bfp(acc[p][2]+qb.x,acc[p][3]+qb.y);
        }
    }
    __syncthreads();

    // Phase 3: attention. warp: head h = wid>>1, row-half mh = wid&1
    const int h=wid>>1, mh=wid&1;
    float sacc[2][8][4];
    #pragma unroll
    for(int mt=0;mt<2;mt++)
        #pragma unroll
        for(int nt=0;nt<8;nt++){
            int i0=mh*32+mt*16+(lane>>2), j=nt*8+(lane&3)*2;
            float2 b0=*(const float2*)(g_BIAS+h*4096+i0*64+j);
            float2 b1=*(const float2*)(g_BIAS+h*4096+(i0+8)*64+j);
            sacc[mt][nt][0]=b0.x;sacc[mt][nt][1]=b0.y;sacc[mt][nt][2]=b1.x;sacc[mt][nt][3]=b1.y;
        }
    #pragma unroll
    for(int kc=0;kc<2;kc++){
        u32 kbase=(u32)h*64u+(u32)kc*32u;
        u32 a[2][4];
        #pragma unroll
        for(int mt=0;mt<2;mt++){
            u32 t=mh*32+mt*16+(lane&15);
            LDSM4(a[mt][0],a[mt][1],a[mt][2],a[mt][3],qB+t*256u+((kbase+(((u32)lane>>4)<<4))^((t&7u)<<4)));
        }
        int g=lane>>3;
        #pragma unroll
        for(int p=0;p<4;p++){
            u32 j=(2*p+(g>>1))*8+(lane&7);
            u32 b0,b1,b2,b3; LDSM4(b0,b1,b2,b3,kTB+j*256u+((kbase+(((u32)g&1u)<<4))^((j&7u)<<4)));
            #pragma unroll
            for(int mt=0;mt<2;mt++){
                MMA(sacc[mt][2*p],a[mt][0],a[mt][1],a[mt][2],a[mt][3],b0,b1);
                MMA(sacc[mt][2*p+1],a[mt][0],a[mt][1],a[mt][2],a[mt][3],b2,b3);
            }
        }
    }
    float inv[2][2];
    #pragma unroll
    for(int mt=0;mt<2;mt++)
        #pragma unroll
        for(int hf=0;hf<2;hf++){
            float m=-1e30f;
            #pragma unroll
            for(int nt=0;nt<8;nt++){m=fmaxf(m,sacc[mt][nt][hf*2]);m=fmaxf(m,sacc[mt][nt][hf*2+1]);}
            m=fmaxf(m,__shfl_xor_sync(~0u,m,1)); m=fmaxf(m,__shfl_xor_sync(~0u,m,2));
            float s=0.f;
            #pragma unroll
            for(int nt=0;nt<8;nt++){
                float e0=__expf(sacc[mt][nt][hf*2]-m), e1=__expf(sacc[mt][nt][hf*2+1]-m);
                sacc[mt][nt][hf*2]=e0; sacc[mt][nt][hf*2+1]=e1; s+=e0+e1;
            }
            s+=__shfl_xor_sync(~0u,s,1); s+=__shfl_xor_sync(~0u,s,2);
            inv[mt][hf]=1.f/s;
        }
    float oacc[2][4][4];
    #pragma unroll
    for(int mt=0;mt<2;mt++)
        #pragma unroll
        for(int p=0;p<4;p++){oacc[mt][p][0]=0;oacc[mt][p][1]=0;oacc[mt][p][2]=0;oacc[mt][p][3]=0;}
    #pragma unroll
    for(int ks=0;ks<4;ks++){
        u32 pa[2][4];
        #pragma unroll
        for(int mt=0;mt<2;mt++){
            pa[mt][0]=bfp(sacc[mt][2*ks][0],sacc[mt][2*ks][1]);
            pa[mt][1]=bfp(sacc[mt][2*ks][2],sacc[mt][2*ks][3]);
            pa[mt][2]=bfp(sacc[mt][2*ks+1][0],sacc[mt][2*ks+1][1]);
            pa[mt][3]=bfp(sacc[mt][2*ks+1][2],sacc[mt][2*ks+1][3]);
        }
        int g=lane>>3;
        #pragma unroll
        for(int p2=0;p2<2;p2++){
            u32 j=(u32)ks*16u+(((u32)g&1u)<<3)+(lane&7);
            u32 colb=2u*((u32)h*32u+(u32)p2*16u)+(((u32)g>>1)<<4);
            u32 b0,b1,b2,b3; LDSM4T(b0,b1,b2,b3,vB+j*256u+(colb^((j&7u)<<4)));
            #pragma unroll
            for(int mt=0;mt<2;mt++){
                MMA(oacc[mt][2*p2],pa[mt][0],pa[mt][1],pa[mt][2],pa[mt][3],b0,b1);
                MMA(oacc[mt][2*p2+1],pa[mt][0],pa[mt][1],pa[mt][2],pa[mt][3],b2,b3);
            }
        }
    }
    #pragma unroll
    for(int mt=0;mt<2;mt++){
        int r0=mh*32+mt*16+(lane>>2), r1=r0+8;
        #pragma unroll
        for(int p=0;p<4;p++){
            int ko=h*32+p*8+(lane&3)*2;
            *(u32*)(smc+0+(u32)r0*256u+(((u32)ko*2u)^((r0&7u)<<4)))=bfp(oacc[mt][p][0]*inv[mt][0],oacc[mt][p][1]*inv[mt][0]);
            *(u32*)(smc+0+(u32)r1*256u+(((u32)ko*2u)^((r1&7u)<<4)))=bfp(oacc[mt][p][2]*inv[mt][1],oacc[mt][p][3]*inv[mt][1]);
        }
    }
    CPA_WAIT0();     // proj weights resident in wbuf0
    __syncthreads();

    // Phase 4: proj (A=outsB tokens @0, B=proj W @wbuf0) + PB -> fout, residual from gmem
    {
        const int mt4=wid>>1, nh4=wid&1;
        float pacc[4][4];
        #pragma unroll
        for(int p=0;p<4;p++){pacc[p][0]=0;pacc[p][1]=0;pacc[p][2]=0;pacc[p][3]=0;}
        #pragma unroll
        for(int kc=0;kc<8;kc++){
            u32 t=mt4*16+(lane&15);
            u32 a0,a1,a2,a3; LDSM4(a0,a1,a2,a3,fB+t*256u+(((u32)kc*32u+(((u32)lane>>4)<<4))^((t&7u)<<4)));
            int g=lane>>3;
            #pragma unroll
            for(int p2=0;p2<2;p2++){
                u32 c=nh4*32+(2*p2+(g>>1))*8+(lane&7);
                u32 b0,b1,b2,b3; LDSM4(b0,b1,b2,b3,wb0+c*256u+(((u32)kc*32u+(((u32)g&1u)<<4))^((c&7u)<<4)));
                MMA(pacc[2*p2],a0,a1,a2,a3,b0,b1); MMA(pacc[2*p2+1],a0,a1,a2,a3,b2,b3);
            }
        }
        float* fout=(float*)(smc+16384);
        int r0=mt4*16+(lane>>2), r1=r0+8;
        #pragma unroll
        for(int p=0;p<4;p++){
            int c=nh4*32+p*8+(lane&3)*2;
            float2 pb=*(const float2*)(g_PB+c);
            fout[r0*68+c]=pacc[p][0]+pb.x; fout[r0*68+c+1]=pacc[p][1]+pb.y;
            fout[r1*68+c]=pacc[p][2]+pb.x; fout[r1*68+c+1]=pacc[p][3]+pb.y;
        }
    }
    __syncthreads();
    {
        const float* fout=(const float*)(smc+16384);
        int c=tid&63, tq0=tid>>6;
        #pragma unroll
        for(int i=0;i<4;i++){
            int tq=i*4+tq0, dz=tq>>2, dy=tq&3, t=tq*4;
            size_t gi=(size_t)c*VOL+base+dz*4096+dy*64;
            float4 cf=*(const float4*)(conv_feat+gi);
            float4 r;
            r.x=fout[(t+0)*68+c]+cf.x; r.y=fout[(t+1)*68+c]+cf.y;
            r.z=fout[(t+2)*68+c]+cf.z; r.w=fout[(t+3)*68+c]+cf.w;
            *(float4*)(out+gi)=r;
        }
    }
}

extern "C" void kernel_launch(void* const* d_in,const int* in_sizes,int n_in,void* d_out,int out_size){
    cudaFuncSetAttribute(fused_attn_kernel,cudaFuncAttributeMaxDynamicSharedMemorySize,98304);
    prep_kernel<<<290,256>>>((const float*)d_in[2],(const float*)d_in[3],(const float*)d_in[4],(const float*)d_in[5],
                             (const float*)d_in[6],(const float*)d_in[7],(const float*)d_in[8],(const float*)d_in[9],
                             (const float*)d_in[10],(const int*)d_in[11]);
    fused_attn_kernel<<<4096,256,98304>>>((const float*)d_in[0],(const float*)d_in[1],(float*)d_out);
}